// round 7
// baseline (speedup 1.0000x reference)
#include <cuda_runtime.h>

#define NG      512
#define W_IMG   256
#define H_IMG   256
#define NEG_HALF_LOG2E (-0.7213475204444817f)   // -0.5 * log2(e)
#define LOG2EPS (-27.0f)                        // skip if max alpha < 2^-27

__device__ __forceinline__ float ex2_approx(float x) {
    float y; asm("ex2.approx.f32 %0, %1;" : "=f"(y) : "f"(x)); return y;
}
__device__ __forceinline__ float lg2_approx(float x) {
    float y; asm("lg2.approx.f32 %0, %1;" : "=f"(y) : "f"(x)); return y;
}
__device__ __forceinline__ float rcp_approx(float x) {
    float y; asm("rcp.approx.f32 %0, %1;" : "=f"(y) : "f"(x)); return y;
}

// Grid = 512 blocks: (row = bid>>1, x-half = bid&1). Each block renders a
// 128-px half-row with 256 threads = 4 groups × 64 threads × 2 px/thread.
// Prep culls each gaussian against the block's exact (row, x-window) footprint
// by maximizing the quadratic exponent over the window (clamped vertex).
// Ordered compaction via (chunk, warp) ballot scan; partial composites are
// combined exactly (compositing is an associative affine map).
__global__ __launch_bounds__(256) void Render_75617194213733_kernel(
    const float* __restrict__ means,    // [NG,2]
    const float* __restrict__ cov,      // [NG,2,2]
    const float* __restrict__ opac,     // [NG]
    const float* __restrict__ colors,   // [NG,3]
    float* __restrict__ out)            // [H,W,3]
{
    __shared__ float4 C[2 * NG];        // [2j]=(mx,ka,kb*dy,kd*dy^2+lop), [2j+1]=(cr,cg,cb,-)
    __shared__ float4 P1[3 * 64];       // partials px1, groups 1..3
    __shared__ float4 P2[3 * 64];       // partials px2, groups 1..3
    __shared__ int    sCnt[16];

    const int tid  = threadIdx.x;
    const int lane = tid & 31;
    const int warp = tid >> 5;
    const int row  = blockIdx.x >> 1;
    const int x0   = (blockIdx.x & 1) << 7;       // 0 or 128
    const float py = (float)row + 0.5f;
    const float dxlo = (float)x0 + 0.5f;          // window in absolute x; mx subtracted later
    const float dxhi = (float)x0 + 127.5f;

    int M;
    // ── Fused prep + (row, x-window) cull + ordered compacted write.
    {
        float4 A[2], B[2];
        bool   kp[2];
        unsigned bl[2];
#pragma unroll
        for (int c = 0; c < 2; c++) {
            const int g = tid + 256 * c;
            float4 cv = ((const float4*)cov)[g];          // a, b, c, d
            float2 mn = ((const float2*)means)[g];
            float  op = opac[g];
            float det = fmaf(cv.x, cv.w, -cv.y * cv.z);
            float s   = NEG_HALF_LOG2E * rcp_approx(det);
            float ka  = s * cv.w;                          // < 0
            float kb  = -s * (cv.y + cv.z);
            float kd  = s * cv.x;                          // < 0
            float lop = lg2_approx(op);
            float dy  = py - mn.y;
            float kbdy = kb * dy;
            float c1   = fmaf(kd * dy, dy, lop);           // kd*dy^2 + log2(op)
            // max of m(dx) = ka*dx^2 + kbdy*dx + c1 over the block's x-window:
            // vertex dx* = -kbdy/(2ka) (ka<0 => maximum), clamped to window.
            float dxv = -kbdy * rcp_approx(ka + ka);
            float dxc = fminf(fmaxf(dxv, dxlo - mn.x), dxhi - mn.x);
            float mmx = fmaf(fmaf(ka, dxc, kbdy), dxc, c1);
            kp[c] = mmx > LOG2EPS;
            bl[c] = __ballot_sync(0xffffffffu, kp[c]);
            if (lane == 0) sCnt[c * 8 + warp] = __popc(bl[c]);
            A[c] = make_float4(mn.x, ka, kbdy, c1);
            B[c] = make_float4(colors[3 * g + 0], colors[3 * g + 1],
                               colors[3 * g + 2], 0.0f);
        }
        __syncthreads();
        int base0 = 0, base1 = 0;
        M = 0;
#pragma unroll
        for (int w = 0; w < 16; w++) {
            int cnt = sCnt[w];
            if (w < warp)     base0 += cnt;
            if (w < 8 + warp) base1 += cnt;
            M += cnt;
        }
        if (kp[0]) {
            int j = base0 + __popc(bl[0] & ((1u << lane) - 1u));
            C[2 * j] = A[0];  C[2 * j + 1] = B[0];
        }
        if (kp[1]) {
            int j = base1 + __popc(bl[1] & ((1u << lane) - 1u));
            C[2 * j] = A[1];  C[2 * j + 1] = B[1];
        }
    }
    __syncthreads();

    const int Mq    = (M + 3) >> 2;
    const int group = tid >> 6;
    const int t     = tid & 63;
    const int j0    = min(group * Mq, M);
    const int j1    = min(j0 + Mq, M);

    const float px = (float)(x0 + 2 * t) + 0.5f;

    float T1 = 1.0f, T2 = 1.0f;
    float r1 = 0.f, g1 = 0.f, b1 = 0.f;
    float r2 = 0.f, g2 = 0.f, b2 = 0.f;

#pragma unroll 4
    for (int j = j0; j < j1; j++) {
        float4 pa = C[2 * j];               // mx, ka, kbdy, c1
        float4 pb = C[2 * j + 1];           // cr, cg, cb, -
        float dx = px - pa.x;
        float t2 = fmaf(pa.y, dx, pa.z);                // ka*dx + kb*dy
        float m1 = fmaf(dx, t2, pa.w);                  // folded exponent at px
        float m2 = (m1 + t2) + fmaf(pa.y, dx, pa.y);    // m(dx+1)

        float a1 = ex2_approx(m1);
        float a2 = ex2_approx(m2);

        float w1 = a1 * T1;
        float w2 = a2 * T2;
        r1 = fmaf(w1, pb.x, r1);
        g1 = fmaf(w1, pb.y, g1);
        b1 = fmaf(w1, pb.z, b1);
        r2 = fmaf(w2, pb.x, r2);
        g2 = fmaf(w2, pb.y, g2);
        b2 = fmaf(w2, pb.z, b2);
        T1 *= 1.0000001f - a1;              // (1 - a) + 1e-7, off the T-chain
        T2 *= 1.0000001f - a2;
    }

    // ── Exact segment combine: C = C_a + T_a * C_b (fold groups 3→2→1→0).
    if (group != 0) {
        int pi = (group - 1) * 64 + t;
        P1[pi] = make_float4(r1, g1, b1, T1);
        P2[pi] = make_float4(r2, g2, b2, T2);
    }
    __syncthreads();
    if (group == 0) {
        float4 q1 = P1[t], q2 = P1[64 + t], q3 = P1[128 + t];
        float rr = fmaf(q2.w, q3.x, q2.x);
        float gg = fmaf(q2.w, q3.y, q2.y);
        float bb = fmaf(q2.w, q3.z, q2.z);
        rr = fmaf(q1.w, rr, q1.x);
        gg = fmaf(q1.w, gg, q1.y);
        bb = fmaf(q1.w, bb, q1.z);
        float R1 = fmaf(T1, rr, r1);
        float G1 = fmaf(T1, gg, g1);
        float B1 = fmaf(T1, bb, b1);

        float4 u1 = P2[t], u2 = P2[64 + t], u3 = P2[128 + t];
        rr = fmaf(u2.w, u3.x, u2.x);
        gg = fmaf(u2.w, u3.y, u2.y);
        bb = fmaf(u2.w, u3.z, u2.z);
        rr = fmaf(u1.w, rr, u1.x);
        gg = fmaf(u1.w, gg, u1.y);
        bb = fmaf(u1.w, bb, u1.z);
        float R2 = fmaf(T2, rr, r2);
        float G2 = fmaf(T2, gg, g2);
        float B2 = fmaf(T2, bb, b2);

        const int base = (row * W_IMG + x0 + 2 * t) * 3;
        float2* o2 = (float2*)(out + base);
        o2[0] = make_float2(R1, G1);
        o2[1] = make_float2(B1, R2);
        o2[2] = make_float2(G2, B2);
    }
}

extern "C" void kernel_launch(void* const* d_in, const int* in_sizes, int n_in,
                              void* d_out, int out_size) {
    const float* means  = nullptr;
    const float* cov    = nullptr;
    const float* opac   = nullptr;
    const float* colors = nullptr;
    for (int i = 0; i < n_in; i++) {
        switch (in_sizes[i]) {
            case NG * 2: means  = (const float*)d_in[i]; break;
            case NG * 4: cov    = (const float*)d_in[i]; break;
            case NG:     opac   = (const float*)d_in[i]; break;
            case NG * 3: colors = (const float*)d_in[i]; break;
            default: break;
        }
    }
    Render_75617194213733_kernel<<<2 * H_IMG, 256>>>(means, cov, opac, colors,
                                                     (float*)d_out);
}